// round 2
// baseline (speedup 1.0000x reference)
#include <cuda_runtime.h>
#include <cstdint>

#define B_SZ 128
#define N_SZ 2048
#define H_SZ 64
#define S_SZ 64

// ---------------- scratch (device globals: allowed) ----------------
__device__ float g_hA[(size_t)B_SZ * N_SZ * H_SZ];   // 64 MB
__device__ float g_hB[(size_t)B_SZ * N_SZ * H_SZ];   // 64 MB
__device__ float g_agg[3 * B_SZ * S_SZ * H_SZ];      // 6 MB  (agg0|agg1|agg2)
__device__ float g_aggW[B_SZ * S_SZ * H_SZ];         // 2 MB

// ---------------- zero kernel ----------------
__global__ void zero_kernel(float* __restrict__ p, int n) {
    int i = blockIdx.x * blockDim.x + threadIdx.x;
    if (i < n) p[i] = 0.f;
}

// ---------------- layer 0: x[B,N,8] @ W0[8,64] -> LN -> relu -> hA, agg0 ----------------
__global__ __launch_bounds__(256)
void layer0_kernel(const float* __restrict__ x,
                   const int* __restrict__ cluster,
                   const float* __restrict__ W0,
                   const float* __restrict__ b0,
                   const float* __restrict__ g,
                   const float* __restrict__ beta,
                   float* __restrict__ hout,
                   float* __restrict__ agg) {
    __shared__ float sX[128 * 8];
    __shared__ float sW0[8 * 64];
    __shared__ float sMax[64 * 64];
    __shared__ int sClu[128];

    const int b = blockIdx.y;
    const int row0 = blockIdx.x * 128;
    const int tid = threadIdx.x;

    // 128 rows * 8 ch = 1024 floats = 256 float4
    ((float4*)sX)[tid] = ((const float4*)(x + ((size_t)b * N_SZ + row0) * 8))[tid];
    if (tid < 128) ((float4*)sW0)[tid] = ((const float4*)W0)[tid];   // 512 floats
    if (tid < 128) sClu[tid] = cluster[(size_t)b * N_SZ + row0 + tid];
#pragma unroll
    for (int i = 0; i < 16; i++) sMax[tid + 256 * i] = 0.f;
    __syncthreads();

    const int warp = tid >> 5, lane = tid & 31;
    const float bc0 = b0[lane], bc1 = b0[lane + 32];
    const float gc0 = g[lane], gc1 = g[lane + 32];
    const float bt0 = beta[lane], bt1 = beta[lane + 32];
    int* sMaxI = (int*)sMax;

    for (int r = warp * 16; r < warp * 16 + 16; r++) {
        float v0 = bc0, v1 = bc1;
#pragma unroll
        for (int k = 0; k < 8; k++) {
            float xv = sX[r * 8 + k];
            v0 = fmaf(xv, sW0[k * 64 + lane], v0);
            v1 = fmaf(xv, sW0[k * 64 + lane + 32], v1);
        }
        float s1 = v0 + v1;
        float s2 = fmaf(v0, v0, v1 * v1);
#pragma unroll
        for (int off = 16; off > 0; off >>= 1) {
            s1 += __shfl_xor_sync(0xffffffffu, s1, off);
            s2 += __shfl_xor_sync(0xffffffffu, s2, off);
        }
        float mu = s1 * 0.015625f;
        float var = fmaf(-mu, mu, s2 * 0.015625f);
        float rs = rsqrtf(var + 1e-5f);
        float o0 = fmaxf(0.f, fmaf((v0 - mu) * rs, gc0, bt0));
        float o1 = fmaxf(0.f, fmaf((v1 - mu) * rs, gc1, bt1));
        size_t base = ((size_t)b * N_SZ + row0 + r) * H_SZ;
        hout[base + lane] = o0;
        hout[base + lane + 32] = o1;
        int s = sClu[r];
        if (o0 > 0.f) atomicMax(&sMaxI[s * 64 + lane], __float_as_int(o0));
        if (o1 > 0.f) atomicMax(&sMaxI[s * 64 + lane + 32], __float_as_int(o1));
    }
    __syncthreads();
    int* gaggI = (int*)(agg + (size_t)b * 4096);
#pragma unroll
    for (int i = 0; i < 16; i++) {
        int idx = tid + 256 * i;
        int v = sMaxI[idx];
        if (v != 0) atomicMax(&gaggI[idx], v);
    }
}

// ---------------- aggW: aggW[b,s,:] = agg[b,s,:] @ Wbot[64,64] + bias ----------------
__global__ __launch_bounds__(256)
void aggw_kernel(const float* __restrict__ agg,
                 const float* __restrict__ Wbot,
                 const float* __restrict__ bias,
                 float* __restrict__ aggW) {
    __shared__ float sA[64 * 65];
    __shared__ float sW[64 * 64];
    const int b = blockIdx.x, tid = threadIdx.x;
    for (int i = tid; i < 4096; i += 256) {
        sA[(i >> 6) * 65 + (i & 63)] = agg[(size_t)b * 4096 + i];
        sW[i] = Wbot[i];
    }
    __syncthreads();
    const int s = tid >> 2;
    const int c0 = (tid & 3) << 4;
    float acc[16];
#pragma unroll
    for (int j = 0; j < 16; j++) acc[j] = 0.f;
#pragma unroll 8
    for (int k = 0; k < 64; k++) {
        float a = sA[s * 65 + k];
#pragma unroll
        for (int j = 0; j < 16; j++) acc[j] = fmaf(a, sW[k * 64 + c0 + j], acc[j]);
    }
#pragma unroll
    for (int j = 0; j < 16; j++)
        aggW[(size_t)b * 4096 + s * 64 + c0 + j] = acc[j] + bias[c0 + j];
}

// ---------------- layers 1/2: h' = LN(hin@Wtop + aggW[cluster]) -> relu -> (hout), agg ----------------
// dynamic smem layout: sW[4096] | sIn[128*66] | sClu[128 ints]
#define SMEM_LAYER ((4096 + 128 * 66 + 128) * 4)

template <bool WRITE_H>
__global__ __launch_bounds__(256)
void layer_kernel(const float* __restrict__ hin,
                  const float* __restrict__ aggW,
                  const int* __restrict__ cluster,
                  const float* __restrict__ Wtop,
                  const float* __restrict__ g,
                  const float* __restrict__ beta,
                  float* __restrict__ hout,
                  float* __restrict__ agg) {
    extern __shared__ float smem[];
    float* sW = smem;                    // 4096 floats: W, then gathered aggW, then segmax
    float* sIn = smem + 4096;            // 128 rows * 66 (padded)
    int* sClu = (int*)(smem + 4096 + 128 * 66);

    const int b = blockIdx.y;
    const int row0 = blockIdx.x * 128;
    const int tid = threadIdx.x;

    {   // W: 4096 floats = 1024 float4
        const float4* src = (const float4*)Wtop;
        float4* dst = (float4*)sW;
#pragma unroll
        for (int i = 0; i < 4; i++) dst[tid + 256 * i] = src[tid + 256 * i];
    }
    {   // input tile: 128x64 floats, stored with row stride 66 (conflict-free)
        const float2* src = (const float2*)(hin + ((size_t)b * N_SZ + row0) * H_SZ);
#pragma unroll
        for (int i = 0; i < 16; i++) {
            int idx = tid + 256 * i;          // 0..4095 float2s
            int r = idx >> 5, j = idx & 31;
            float2 v = src[idx];
            sIn[r * 66 + j * 2] = v.x;
            sIn[r * 66 + j * 2 + 1] = v.y;
        }
    }
    if (tid < 128) sClu[tid] = cluster[(size_t)b * N_SZ + row0 + tid];
    __syncthreads();

    // GEMM: 128 rows x 64 cols, k=64. thread = (tx: 16 col-groups, ty: 16 row-groups)
    const int tx = tid & 15, ty = tid >> 4;
    float acc[8][4];
#pragma unroll
    for (int i = 0; i < 8; i++)
#pragma unroll
        for (int j = 0; j < 4; j++) acc[i][j] = 0.f;

#pragma unroll 8
    for (int k = 0; k < 64; k++) {
        float4 bv = *(const float4*)&sW[k * 64 + tx * 4];
#pragma unroll
        for (int i = 0; i < 8; i++) {
            float a = sIn[(ty + 16 * i) * 66 + k];
            acc[i][0] = fmaf(a, bv.x, acc[i][0]);
            acc[i][1] = fmaf(a, bv.y, acc[i][1]);
            acc[i][2] = fmaf(a, bv.z, acc[i][2]);
            acc[i][3] = fmaf(a, bv.w, acc[i][3]);
        }
    }
    __syncthreads();

    {   // stage aggW[b] (gathered bias table, bias already folded) into sW
        const float4* src = (const float4*)(aggW + (size_t)b * 4096);
        float4* dst = (float4*)sW;
#pragma unroll
        for (int i = 0; i < 4; i++) dst[tid + 256 * i] = src[tid + 256 * i];
    }
    __syncthreads();

#pragma unroll
    for (int i = 0; i < 8; i++) {
        int s = sClu[ty + 16 * i];
        const float* gr = &sW[s * 64 + tx * 4];
        acc[i][0] += gr[0];
        acc[i][1] += gr[1];
        acc[i][2] += gr[2];
        acc[i][3] += gr[3];
    }
    // stash pre-LN h back to sIn
#pragma unroll
    for (int i = 0; i < 8; i++) {
        float* p = &sIn[(ty + 16 * i) * 66 + tx * 4];
        ((float2*)p)[0] = make_float2(acc[i][0], acc[i][1]);
        ((float2*)p)[1] = make_float2(acc[i][2], acc[i][3]);
    }
    __syncthreads();

    // zero segmax region (reuse sW)
#pragma unroll
    for (int i = 0; i < 16; i++) sW[tid + 256 * i] = 0.f;
    __syncthreads();

    const int warp = tid >> 5, lane = tid & 31;
    const float gc0 = g[lane], gc1 = g[lane + 32];
    const float bt0 = beta[lane], bt1 = beta[lane + 32];
    int* sMaxI = (int*)sW;

    for (int r = warp * 16; r < warp * 16 + 16; r++) {
        float v0 = sIn[r * 66 + lane];
        float v1 = sIn[r * 66 + lane + 32];
        float s1 = v0 + v1;
        float s2 = fmaf(v0, v0, v1 * v1);
#pragma unroll
        for (int off = 16; off > 0; off >>= 1) {
            s1 += __shfl_xor_sync(0xffffffffu, s1, off);
            s2 += __shfl_xor_sync(0xffffffffu, s2, off);
        }
        float mu = s1 * 0.015625f;
        float var = fmaf(-mu, mu, s2 * 0.015625f);
        float rs = rsqrtf(var + 1e-5f);
        float o0 = fmaxf(0.f, fmaf((v0 - mu) * rs, gc0, bt0));
        float o1 = fmaxf(0.f, fmaf((v1 - mu) * rs, gc1, bt1));
        if (WRITE_H) {
            size_t base = ((size_t)b * N_SZ + row0 + r) * H_SZ;
            hout[base + lane] = o0;
            hout[base + lane + 32] = o1;
        }
        int s = sClu[r];
        if (o0 > 0.f) atomicMax(&sMaxI[s * 64 + lane], __float_as_int(o0));
        if (o1 > 0.f) atomicMax(&sMaxI[s * 64 + lane + 32], __float_as_int(o1));
    }
    __syncthreads();

    int* gaggI = (int*)(agg + (size_t)b * 4096);
#pragma unroll
    for (int i = 0; i < 16; i++) {
        int idx = tid + 256 * i;
        int v = sMaxI[idx];
        if (v != 0) atomicMax(&gaggI[idx], v);
    }
}

// ---------------- final: out[b,s,c] = out[b,s,c+64] = agg2[b,s,c]/max(||.||_segs, 1e-12) ----------------
__global__ __launch_bounds__(256)
void final_kernel(const float* __restrict__ agg2, float* __restrict__ out) {
    __shared__ float sA[64 * 64];
    __shared__ float sInv[64];
    const int b = blockIdx.x, tid = threadIdx.x;
    for (int i = tid; i < 4096; i += 256) sA[i] = agg2[(size_t)b * 4096 + i];
    __syncthreads();
    if (tid < 64) {
        float nsum = 0.f;
#pragma unroll 8
        for (int s = 0; s < 64; s++) {
            float v = sA[s * 64 + tid];
            nsum = fmaf(v, v, nsum);
        }
        float nrm = sqrtf(nsum);
        sInv[tid] = 1.f / fmaxf(nrm, 1e-12f);
    }
    __syncthreads();
    for (int i = tid; i < 8192; i += 256) {
        int s = i >> 7, ch = i & 127, c = ch & 63;
        out[(size_t)b * 8192 + i] = sA[s * 64 + c] * sInv[c];
    }
}

// ---------------- launch ----------------
extern "C" void kernel_launch(void* const* d_in, const int* in_sizes, int n_in,
                              void* d_out, int out_size) {
    const float* x = (const float*)d_in[0];
    const int* cluster = (const int*)d_in[1];
    const float* W0 = (const float*)d_in[2];
    const float* b0 = (const float*)d_in[3];
    const float* g0 = (const float*)d_in[4];
    const float* be0 = (const float*)d_in[5];
    const float* W1 = (const float*)d_in[6];
    const float* b1 = (const float*)d_in[7];
    const float* g1 = (const float*)d_in[8];
    const float* be1 = (const float*)d_in[9];
    const float* W2 = (const float*)d_in[10];
    const float* b2 = (const float*)d_in[11];
    const float* g2 = (const float*)d_in[12];
    const float* be2 = (const float*)d_in[13];
    float* out = (float*)d_out;

    float *hA, *hB, *agg, *aggW;
    cudaGetSymbolAddress((void**)&hA, g_hA);
    cudaGetSymbolAddress((void**)&hB, g_hB);
    cudaGetSymbolAddress((void**)&agg, g_agg);
    cudaGetSymbolAddress((void**)&aggW, g_aggW);
    float* agg0 = agg;
    float* agg1 = agg + (size_t)B_SZ * 4096;
    float* agg2 = agg + (size_t)2 * B_SZ * 4096;

    cudaFuncSetAttribute(layer_kernel<true>, cudaFuncAttributeMaxDynamicSharedMemorySize, SMEM_LAYER);
    cudaFuncSetAttribute(layer_kernel<false>, cudaFuncAttributeMaxDynamicSharedMemorySize, SMEM_LAYER);

    const int nz = 3 * B_SZ * 4096;
    zero_kernel<<<(nz + 255) / 256, 256>>>(agg, nz);

    dim3 grid(N_SZ / 128, B_SZ);
    layer0_kernel<<<grid, 256>>>(x, cluster, W0, b0, g0, be0, hA, agg0);
    aggw_kernel<<<B_SZ, 256>>>(agg0, W1 + 64 * 64, b1, aggW);
    layer_kernel<true><<<grid, 256, SMEM_LAYER>>>(hA, aggW, cluster, W1, g1, be1, hB, agg1);
    aggw_kernel<<<B_SZ, 256>>>(agg1, W2 + 64 * 64, b2, aggW);
    layer_kernel<false><<<grid, 256, SMEM_LAYER>>>(hB, aggW, cluster, W2, g2, be2, nullptr, agg2);
    final_kernel<<<B_SZ, 256>>>(agg2, out);
}